// round 1
// baseline (speedup 1.0000x reference)
#include <cuda_runtime.h>
#include <cstdint>
#include <cstddef>

// Problem constants
#define BATCH 32
#define NREG  36
#define DIM   2048
#define RANK  512
#define KTOT  1024              // 2*RANK (feat || coord)
#define BN    (BATCH * NREG)    // 1152

// Scratch: G = i-side fused projections [BN][1024] (cols 0:512 = uf, 512:1024 = uc)
//          H = j-side fused projections [BN][1024] (cols 0:512 = vf, 512:1024 = vc)
__device__ float g_G[BN * KTOT];
__device__ float g_H[BN * KTOT];

__device__ __forceinline__ uint32_t f2tf32(float x) {
    uint32_t r;
    asm("cvt.rna.tf32.f32 %0, %1;" : "=r"(r) : "f"(x));
    return r;
}

__device__ __forceinline__ void mma_tf32(float c[4], const uint32_t a[4], const uint32_t b[2]) {
    asm volatile(
        "mma.sync.aligned.m16n8k8.row.col.f32.tf32.tf32.f32 "
        "{%0,%1,%2,%3}, {%4,%5,%6,%7}, {%8,%9}, {%0,%1,%2,%3};\n"
        : "+f"(c[0]), "+f"(c[1]), "+f"(c[2]), "+f"(c[3])
        : "r"(a[0]), "r"(a[1]), "r"(a[2]), "r"(a[3]), "r"(b[0]), "r"(b[1]));
}

// ---------------------------------------------------------------------------
// Coord projections: G[:,512+n] = coords @ U_coord, H[:,512+n] = coords @ V_coord
// K=4, trivial FP32.
// ---------------------------------------------------------------------------
__global__ void coord_stage(const float* __restrict__ coords,
                            const float* __restrict__ Uc,
                            const float* __restrict__ Vc) {
    int idx = blockIdx.x * blockDim.x + threadIdx.x;
    if (idx >= BN * RANK) return;
    int row = idx >> 9;       // / 512
    int n   = idx & 511;
    const float* c = coords + row * 4;
    float c0 = c[0], c1 = c[1], c2 = c[2], c3 = c[3];
    g_G[(size_t)row * KTOT + RANK + n] =
        c0 * Uc[n] + c1 * Uc[512 + n] + c2 * Uc[1024 + n] + c3 * Uc[1536 + n];
    g_H[(size_t)row * KTOT + RANK + n] =
        c0 * Vc[n] + c1 * Vc[512 + n] + c2 * Vc[1024 + n] + c3 * Vc[1536 + n];
}

// ---------------------------------------------------------------------------
// Stage 1: C[1152, 1024] = mm[1152,2048] @ [U_feat | V_feat], tf32 MMA.
// Virtual col n < 512 -> U_feat -> G[:, n];  n >= 512 -> V_feat -> H[:, n-512].
// CTA tile 128x128, K-chunk 32. 8 warps as 4(M) x 2(N): warp tile 32x64.
// ---------------------------------------------------------------------------
__global__ __launch_bounds__(256, 2)
void stage1_feat(const float* __restrict__ mm,
                 const float* __restrict__ Uf,
                 const float* __restrict__ Vf) {
    __shared__ uint32_t As[128][36];   // [m][k], padded stride 36 (bank-safe)
    __shared__ uint32_t Bs[32][136];   // [k][n], padded stride 136 (bank-safe)

    const int tid = threadIdx.x;
    const int lane = tid & 31, wid = tid >> 5;
    const int warpM = wid & 3, warpN = wid >> 2;
    const int mblk = blockIdx.y * 128;
    const int nblk = blockIdx.x * 128;

    const float* W = (nblk < 512) ? (Uf + nblk) : (Vf + (nblk - 512));

    float acc[2][8][4];
#pragma unroll
    for (int mt = 0; mt < 2; mt++)
#pragma unroll
        for (int nt = 0; nt < 8; nt++)
#pragma unroll
            for (int q = 0; q < 4; q++) acc[mt][nt][q] = 0.f;

    for (int kc = 0; kc < DIM; kc += 32) {
        // Load A tile: mm rows (no transpose, [m][k] natural).
#pragma unroll
        for (int p = 0; p < 4; p++) {
            int m  = (tid >> 3) + 32 * p;
            int k4 = (tid & 7) * 4;
            float4 v = *(const float4*)(mm + (size_t)(mblk + m) * DIM + kc + k4);
            uint4 t = make_uint4(f2tf32(v.x), f2tf32(v.y), f2tf32(v.z), f2tf32(v.w));
            *(uint4*)&As[m][k4] = t;
        }
        // Load B tile: W rows ([k][n] natural).
#pragma unroll
        for (int p = 0; p < 4; p++) {
            int k = wid + 8 * p;
            float4 v = *(const float4*)(W + (size_t)(kc + k) * 512 + lane * 4);
            uint4 t = make_uint4(f2tf32(v.x), f2tf32(v.y), f2tf32(v.z), f2tf32(v.w));
            *(uint4*)&Bs[k][lane * 4] = t;
        }
        __syncthreads();

#pragma unroll
        for (int kk = 0; kk < 4; kk++) {
            uint32_t a[2][4];
#pragma unroll
            for (int mt = 0; mt < 2; mt++) {
                int mb = warpM * 32 + mt * 16;
                int r = lane >> 2, kq = kk * 8 + (lane & 3);
                a[mt][0] = As[mb + r][kq];
                a[mt][1] = As[mb + r + 8][kq];
                a[mt][2] = As[mb + r][kq + 4];
                a[mt][3] = As[mb + r + 8][kq + 4];
            }
#pragma unroll
            for (int nt = 0; nt < 8; nt++) {
                int nb = warpN * 64 + nt * 8;
                uint32_t b[2];
                b[0] = Bs[kk * 8 + (lane & 3)][nb + (lane >> 2)];
                b[1] = Bs[kk * 8 + (lane & 3) + 4][nb + (lane >> 2)];
                mma_tf32(acc[0][nt], a[0], b);
                mma_tf32(acc[1][nt], a[1], b);
            }
        }
        __syncthreads();
    }

    // Epilogue: scatter C into G or H.
    float* Cout = (nblk < 512) ? g_G : g_H;
    const int colbase = (nblk < 512) ? nblk : (nblk - 512);
#pragma unroll
    for (int mt = 0; mt < 2; mt++)
#pragma unroll
        for (int nt = 0; nt < 8; nt++)
#pragma unroll
            for (int rh = 0; rh < 2; rh++)
#pragma unroll
                for (int e = 0; e < 2; e++) {
                    int row = mblk + warpM * 32 + mt * 16 + (lane >> 2) + rh * 8;
                    int col = colbase + warpN * 64 + nt * 8 + (lane & 3) * 2 + e;
                    Cout[(size_t)row * KTOT + col] = acc[mt][nt][rh * 2 + e];
                }
}

// ---------------------------------------------------------------------------
// Main kernel: per (b, group-of-4 i's), C[d, n] = P^T @ Z where
//   Z[n, r] = relu(G[b,i(n),r] * H[b,j(n),r]),  n = iloc*36 + j  (144 cols)
// CTA tile: M=128 (d), N=144, K=1024 in chunks of 32.
// 8 warps as 4(M) x 2(N): warp tile 32 x 72.
// Epilogue: max over j within each 36-group + residual.
// ---------------------------------------------------------------------------
__global__ __launch_bounds__(256, 2)
void pairwise_main(const float* __restrict__ mm,
                   const float* __restrict__ Pf,
                   const float* __restrict__ Pc,
                   float* __restrict__ out) {
    __shared__ uint32_t As[32][136];   // [k][m]  (A = P^T, native row = k)
    __shared__ uint32_t Zs[144][36];   // [n][k]

    const int tid = threadIdx.x;
    const int lane = tid & 31, wid = tid >> 5;
    const int warpM = wid & 3, warpN = wid >> 2;
    const int d0 = blockIdx.x * 128;
    const int grp = blockIdx.y;         // 0..287
    const int b  = grp / 9;
    const int i0 = (grp % 9) * 4;

    float acc[2][9][4];
#pragma unroll
    for (int mt = 0; mt < 2; mt++)
#pragma unroll
        for (int nt = 0; nt < 9; nt++)
#pragma unroll
            for (int q = 0; q < 4; q++) acc[mt][nt][q] = 0.f;

    for (int rc = 0; rc < KTOT; rc += 32) {
        const float* P = (rc < RANK) ? (Pf + (size_t)rc * DIM)
                                     : (Pc + (size_t)(rc - RANK) * DIM);
        // A tile: 32 k-rows x 128 d cols, coalesced float4.
#pragma unroll
        for (int p = 0; p < 4; p++) {
            int k = wid + 8 * p;
            float4 v = *(const float4*)(P + (size_t)k * DIM + d0 + lane * 4);
            uint4 t = make_uint4(f2tf32(v.x), f2tf32(v.y), f2tf32(v.z), f2tf32(v.w));
            *(uint4*)&As[k][lane * 4] = t;
        }
        // Z tile build: one warp per n-row per pass, lanes along k (coalesced).
#pragma unroll
        for (int pass = 0; pass < 18; pass++) {
            int n = pass * 8 + wid;
            int iloc = n / 36, j = n % 36;
            float g = g_G[(size_t)(b * 36 + i0 + iloc) * KTOT + rc + lane];
            float h = g_H[(size_t)(b * 36 + j) * KTOT + rc + lane];
            float z = g * h;
            z = z > 0.f ? z : 0.f;
            Zs[n][lane] = f2tf32(z);
        }
        __syncthreads();

#pragma unroll
        for (int kk = 0; kk < 4; kk++) {
            uint32_t a[2][4];
#pragma unroll
            for (int mt = 0; mt < 2; mt++) {
                int mb = warpM * 32 + mt * 16;
                int r = lane >> 2, kq = kk * 8 + (lane & 3);
                a[mt][0] = As[kq][mb + r];
                a[mt][1] = As[kq][mb + r + 8];
                a[mt][2] = As[kq + 4][mb + r];
                a[mt][3] = As[kq + 4][mb + r + 8];
            }
#pragma unroll
            for (int nt = 0; nt < 9; nt++) {
                int nb = warpN * 72 + nt * 8;
                uint32_t bb[2];
                bb[0] = Zs[nb + (lane >> 2)][kk * 8 + (lane & 3)];
                bb[1] = Zs[nb + (lane >> 2)][kk * 8 + (lane & 3) + 4];
                mma_tf32(acc[0][nt], a[0], bb);
                mma_tf32(acc[1][nt], a[1], bb);
            }
        }
        __syncthreads();
    }

    // ---- Epilogue: max over j within each 36-group, + residual ----
    const int s = lane & 3;
    float gmax[2][2][2];   // [mt][rowhalf][group]
#pragma unroll
    for (int mt = 0; mt < 2; mt++)
#pragma unroll
        for (int rh = 0; rh < 2; rh++)
#pragma unroll
            for (int g2 = 0; g2 < 2; g2++) gmax[mt][rh][g2] = -1e30f;

#pragma unroll
    for (int nt = 0; nt < 9; nt++) {
#pragma unroll
        for (int e = 0; e < 2; e++) {
            int nloc = nt * 8 + s * 2 + e;      // 0..71 within warp N-range
            int g2 = (nloc >= 36) ? 1 : 0;
#pragma unroll
            for (int mt = 0; mt < 2; mt++)
#pragma unroll
                for (int rh = 0; rh < 2; rh++) {
                    float v = acc[mt][nt][rh * 2 + e];
                    gmax[mt][rh][g2] = fmaxf(gmax[mt][rh][g2], v);
                }
        }
    }
    // Reduce across the 4 lanes of the quad (same d-row, different n's).
#pragma unroll
    for (int mt = 0; mt < 2; mt++)
#pragma unroll
        for (int rh = 0; rh < 2; rh++)
#pragma unroll
            for (int g2 = 0; g2 < 2; g2++) {
                float v = gmax[mt][rh][g2];
                v = fmaxf(v, __shfl_xor_sync(0xffffffffu, v, 1));
                v = fmaxf(v, __shfl_xor_sync(0xffffffffu, v, 2));
                gmax[mt][rh][g2] = v;
            }

    if (s < 2) {
        int iglob = i0 + warpN * 2 + s;          // s selects group
        size_t rowbase = (size_t)(b * 36 + iglob) * DIM;
#pragma unroll
        for (int mt = 0; mt < 2; mt++)
#pragma unroll
            for (int rh = 0; rh < 2; rh++) {
                int d = d0 + warpM * 32 + mt * 16 + (lane >> 2) + rh * 8;
                out[rowbase + d] = gmax[mt][rh][s] + mm[rowbase + d];
            }
    }
}

// ---------------------------------------------------------------------------
extern "C" void kernel_launch(void* const* d_in, const int* in_sizes, int n_in,
                              void* d_out, int out_size) {
    const float* mm     = (const float*)d_in[0];
    const float* coords = (const float*)d_in[1];
    const float* Uf     = (const float*)d_in[2];
    const float* Vf     = (const float*)d_in[3];
    const float* Pf     = (const float*)d_in[4];
    const float* Uc     = (const float*)d_in[5];
    const float* Vc     = (const float*)d_in[6];
    const float* Pc     = (const float*)d_in[7];
    float* out = (float*)d_out;

    coord_stage<<<(BN * RANK + 255) / 256, 256>>>(coords, Uc, Vc);

    dim3 g1(8, 9);                 // N=1024/128, M=1152/128
    stage1_feat<<<g1, 256>>>(mm, Uf, Vf);

    dim3 g2(16, 288);              // D/128, (B*N)/4
    pairwise_main<<<g2, 256>>>(mm, Pf, Pc, out);
}